// round 9
// baseline (speedup 1.0000x reference)
#include <cuda_runtime.h>
#include <cuda_bf16.h>
#include <cstdint>

// Fused: posenc -> (enc @ W^T) -> softmax(x3 @ cent^T) -> weighted contraction.
// - 2 points/thread: each broadcast LDS.128 of W feeds 4 FFMA2 (crossbar 50%
//   of the binding FMA-pipe time).
// - packed f32x2 FMA throughout (2x fp32 FMA throughput on sm_103a).
// - W double-buffered through SMEM via cp.async: chunk ch+1 copies while
//   chunk ch computes.
// - softmax normalizer folded into the main loop (shift-invariant, scores small).
// - posenc uses two sincos anchors (x, 8x): <=2 double-angle steps per freq,
//   error amplification <=16x.

#define NCLUST   256
#define ECODE    72      // D*2*F = 6*12
#define CHUNK    16      // clusters per SMEM buffer
#define NCHUNKS  (NCLUST / CHUNK)
#define CFLOATS  (CHUNK * 3 * ECODE)     // 3456 floats per chunk (13.5 KB)
#define CVEC4    (CFLOATS / 4)           // 864 16B packets per chunk
#define TPB      128
#define PTS      2
#define TILE     (TPB * PTS)

typedef unsigned long long u64;

__device__ __forceinline__ u64 ffma2(u64 a, u64 b, u64 c) {
    u64 d;
    asm("fma.rn.f32x2 %0, %1, %2, %3;" : "=l"(d) : "l"(a), "l"(b), "l"(c));
    return d;
}

__device__ __forceinline__ u64 pack2(float lo, float hi) {
    u64 d;
    asm("mov.b64 %0, {%1, %2};" : "=l"(d) : "f"(lo), "f"(hi));
    return d;
}

__device__ __forceinline__ float hsum2(u64 a) {
    float lo, hi;
    asm("mov.b64 {%0, %1}, %2;" : "=f"(lo), "=f"(hi) : "l"(a));
    return lo + hi;
}

__device__ __forceinline__ void cp_async16(uint32_t saddr, const void* gptr) {
    asm volatile("cp.async.cg.shared.global [%0], [%1], 16;"
                 :: "r"(saddr), "l"(gptr));
}
__device__ __forceinline__ void cp_async_commit() {
    asm volatile("cp.async.commit_group;");
}
__device__ __forceinline__ void cp_async_wait_all() {
    asm volatile("cp.async.wait_group 0;" ::: "memory");
}

// posenc for one point: x[6] -> 36 packed f32x2 (per-dim: s0..s5 then c0..c5).
// Anchors at f=0 (x) and f=3 (8x); f=1,2 and f=4,5 via <=2 double-angle steps.
__device__ __forceinline__ void posenc6(const float* __restrict__ xr, u64* e2) {
    #pragma unroll
    for (int d = 0; d < 6; ++d) {
        float s[6], c[6];
        sincosf(xr[d], &s[0], &c[0]);
        sincosf(8.0f * xr[d], &s[3], &c[3]);
        #pragma unroll
        for (int f = 1; f < 3; ++f) {
            s[f] = 2.0f * s[f - 1] * c[f - 1];             // sin(2a)
            c[f] = fmaf(2.0f * c[f - 1], c[f - 1], -1.0f); // cos(2a)
        }
        #pragma unroll
        for (int f = 4; f < 6; ++f) {
            s[f] = 2.0f * s[f - 1] * c[f - 1];
            c[f] = fmaf(2.0f * c[f - 1], c[f - 1], -1.0f);
        }
        e2[d * 6 + 0] = pack2(s[0], s[1]);
        e2[d * 6 + 1] = pack2(s[2], s[3]);
        e2[d * 6 + 2] = pack2(s[4], s[5]);
        e2[d * 6 + 3] = pack2(c[0], c[1]);
        e2[d * 6 + 4] = pack2(c[2], c[3]);
        e2[d * 6 + 5] = pack2(c[4], c[5]);
    }
}

__global__ __launch_bounds__(TPB)
void clusterised_attn_kernel(const float* __restrict__ X,
                             const float* __restrict__ LM,    // [768, 72] row-major
                             const float* __restrict__ cent,  // [256, 3]
                             float* __restrict__ out,         // [N, 3]
                             int N)
{
    __shared__ __align__(16) float sW[2][CFLOATS];   // 2 x 13.5 KB
    __shared__ float scx[NCLUST], scy[NCLUST], scz[NCLUST];

    const int tid = threadIdx.x;

    // ---- kick off copy of chunk 0 immediately (overlaps with posenc)
    {
        const uint32_t sdst = (uint32_t)__cvta_generic_to_shared(&sW[0][0]);
        const float4* src = (const float4*)LM;
        #pragma unroll 1
        for (int i = tid; i < CVEC4; i += TPB)
            cp_async16(sdst + (uint32_t)i * 16u, src + i);
        cp_async_commit();
    }

    // centroids -> SMEM (transposed)
    for (int i = tid; i < NCLUST; i += TPB) {
        scx[i] = cent[i * 3 + 0];
        scy[i] = cent[i * 3 + 1];
        scz[i] = cent[i * 3 + 2];
    }

    const int base = blockIdx.x * TILE;
    const int n0 = base + tid;
    const int n1 = base + TPB + tid;
    const bool v0 = (n0 < N), v1 = (n1 < N);
    const int m0 = v0 ? n0 : (N - 1);
    const int m1 = v1 ? n1 : (N - 1);

    float xa[6], xb[6];
    #pragma unroll
    for (int d = 0; d < 6; ++d) xa[d] = X[m0 * 6 + d];
    #pragma unroll
    for (int d = 0; d < 6; ++d) xb[d] = X[m1 * 6 + d];

    u64 eA[36], eB[36];
    posenc6(xa, eA);
    posenc6(xb, eB);

    const float ax = xa[0], ay = xa[1], az = xa[2];
    const float bx = xb[0], by = xb[1], bz = xb[2];

    cp_async_wait_all();
    __syncthreads();   // chunk 0 + centroids ready

    u64 acA0 = 0ull, acA1 = 0ull, acA2 = 0ull;
    u64 acB0 = 0ull, acB1 = 0ull, acB2 = 0ull;
    float ZA = 0.0f, ZB = 0.0f;

    #pragma unroll 1
    for (int ch = 0; ch < NCHUNKS; ++ch) {
        const int cur = ch & 1;

        // prefetch next chunk into the other buffer (overlaps with compute).
        // Safe: the __syncthreads closing iteration ch-1 is the last reader
        // of buffer cur^1.
        if (ch < NCHUNKS - 1) {
            const uint32_t sdst =
                (uint32_t)__cvta_generic_to_shared(&sW[cur ^ 1][0]);
            const float4* src = (const float4*)(LM + (ch + 1) * CFLOATS);
            #pragma unroll 1
            for (int i = tid; i < CVEC4; i += TPB)
                cp_async16(sdst + (uint32_t)i * 16u, src + i);
            cp_async_commit();
        }

        const float* wbuf = sW[cur];

        #pragma unroll 1
        for (int c = 0; c < CHUNK; ++c) {
            const int cg = ch * CHUNK + c;
            const float cx = scx[cg], cy = scy[cg], cz = scz[cg];
            const float wA = __expf(fmaf(ax, cx, fmaf(ay, cy, az * cz)));
            const float wB = __expf(fmaf(bx, cx, fmaf(by, cy, bz * cz)));
            ZA += wA;
            ZB += wB;
            const u64 wA2 = pack2(wA, wA);
            const u64 wB2 = pack2(wB, wB);

            const ulonglong2* r0 = (const ulonglong2*)(wbuf + c * 3 * ECODE);
            const ulonglong2* r1 = (const ulonglong2*)(wbuf + c * 3 * ECODE + ECODE);
            const ulonglong2* r2 = (const ulonglong2*)(wbuf + c * 3 * ECODE + 2 * ECODE);

            u64 tA0 = 0ull, tA1 = 0ull, tA2 = 0ull;
            u64 tB0 = 0ull, tB1 = 0ull, tB2 = 0ull;
            #pragma unroll
            for (int j = 0; j < 18; ++j) {
                const ulonglong2 q0 = r0[j];
                const ulonglong2 q1 = r1[j];
                const ulonglong2 q2 = r2[j];
                const u64 eAa = eA[2 * j], eAb = eA[2 * j + 1];
                const u64 eBa = eB[2 * j], eBb = eB[2 * j + 1];
                // 6 rotating accumulators -> dep distance >= lat
                tA0 = ffma2(eAa, q0.x, tA0);
                tA1 = ffma2(eAa, q1.x, tA1);
                tA2 = ffma2(eAa, q2.x, tA2);
                tB0 = ffma2(eBa, q0.x, tB0);
                tB1 = ffma2(eBa, q1.x, tB1);
                tB2 = ffma2(eBa, q2.x, tB2);
                tA0 = ffma2(eAb, q0.y, tA0);
                tA1 = ffma2(eAb, q1.y, tA1);
                tA2 = ffma2(eAb, q2.y, tA2);
                tB0 = ffma2(eBb, q0.y, tB0);
                tB1 = ffma2(eBb, q1.y, tB1);
                tB2 = ffma2(eBb, q2.y, tB2);
            }
            acA0 = ffma2(wA2, tA0, acA0);
            acA1 = ffma2(wA2, tA1, acA1);
            acA2 = ffma2(wA2, tA2, acA2);
            acB0 = ffma2(wB2, tB0, acB0);
            acB1 = ffma2(wB2, tB1, acB1);
            acB2 = ffma2(wB2, tB2, acB2);
        }

        if (ch < NCHUNKS - 1) {
            cp_async_wait_all();
            __syncthreads();   // next buffer filled, current fully consumed
        }
    }

    if (v0) {
        const float invZ = 1.0f / ZA;
        out[n0 * 3 + 0] = hsum2(acA0) * invZ;
        out[n0 * 3 + 1] = hsum2(acA1) * invZ;
        out[n0 * 3 + 2] = hsum2(acA2) * invZ;
    }
    if (v1) {
        const float invZ = 1.0f / ZB;
        out[n1 * 3 + 0] = hsum2(acB0) * invZ;
        out[n1 * 3 + 1] = hsum2(acB1) * invZ;
        out[n1 * 3 + 2] = hsum2(acB2) * invZ;
    }
}

extern "C" void kernel_launch(void* const* d_in, const int* in_sizes, int n_in,
                              void* d_out, int out_size) {
    const float* X    = (const float*)d_in[0];   // [N, 6]
    const float* LM   = (const float*)d_in[1];   // [768, 72]
    const float* cent = (const float*)d_in[2];   // [256, 3]
    float* out = (float*)d_out;                  // [N, 3]

    const int N = in_sizes[0] / 6;
    const int grid = (N + TILE - 1) / TILE;
    clusterised_attn_kernel<<<grid, TPB>>>(X, LM, cent, out, N);
}